// round 2
// baseline (speedup 1.0000x reference)
#include <cuda_runtime.h>
#include <math.h>
#include <stdint.h>

// ---------------------------------------------------------------------------
// Shapes (fixed for this problem)
//   x:    (64, 1, 112, 112)
//   s1: conv 1->32 s1  @112 ; BN ; deform(32, off 64ch) @112
//   s2: conv 32->64 s2 @112->56 ; BN ; deform(64, off 128ch) @56
//   s3: conv 64->128 s1 @56 ; BN ; deform(128, off 256ch) @56
//   s4: conv 128->128 s2 @56->28 ; BN ; pool+fc+softmax -> (64,10) f32
// ---------------------------------------------------------------------------

#define B_ 64

// ---- scratch buffer (single __device__ global; offsets in floats) ----------
constexpr size_t SZ_A1   = (size_t)B_ * 32 * 112 * 112;   // 25,690,112
constexpr size_t SZ_OFF1 = (size_t)B_ * 64 * 112 * 112;   // 51,380,224
constexpr size_t SZ_D1   = SZ_A1;
constexpr size_t SZ_A2   = (size_t)B_ * 64 * 56 * 56;     // 12,845,056
constexpr size_t SZ_OFF2 = (size_t)B_ * 128 * 56 * 56;    // 25,690,112
constexpr size_t SZ_D2   = SZ_A2;
constexpr size_t SZ_A3   = (size_t)B_ * 128 * 56 * 56;
constexpr size_t SZ_OFF3 = (size_t)B_ * 256 * 56 * 56;    // 51,380,224
constexpr size_t SZ_D3   = SZ_A3;
constexpr size_t SZ_A4   = (size_t)B_ * 128 * 28 * 28;    // 6,422,528
constexpr size_t SZ_PART = (size_t)128 * 64;              // per (c, slice)
constexpr size_t SZ_SS   = 128;

constexpr size_t OFF_A1   = 0;
constexpr size_t OFF_OFF1 = OFF_A1   + SZ_A1;
constexpr size_t OFF_D1   = OFF_OFF1 + SZ_OFF1;
constexpr size_t OFF_A2   = OFF_D1   + SZ_D1;
constexpr size_t OFF_OFF2 = OFF_A2   + SZ_A2;
constexpr size_t OFF_D2   = OFF_OFF2 + SZ_OFF2;
constexpr size_t OFF_A3   = OFF_D2   + SZ_D2;
constexpr size_t OFF_OFF3 = OFF_A3   + SZ_A3;
constexpr size_t OFF_D3   = OFF_OFF3 + SZ_OFF3;
constexpr size_t OFF_A4   = OFF_D3   + SZ_D3;
constexpr size_t OFF_PSUM = OFF_A4   + SZ_A4;
constexpr size_t OFF_PSQ  = OFF_PSUM + SZ_PART;
constexpr size_t OFF_SC   = OFF_PSQ  + SZ_PART;
constexpr size_t OFF_SH   = OFF_SC   + SZ_SS;
constexpr size_t TOTAL_F  = OFF_SH   + SZ_SS;

__device__ float g_buf[TOTAL_F];

// ---------------------------------------------------------------------------
// Direct 3x3 conv, pad=1. Output tile 64(x) x 16(y), 256 threads,
// each thread computes 4 horizontally-adjacent outputs.
// ---------------------------------------------------------------------------
template <int STRIDE>
__global__ __launch_bounds__(256)
void conv3x3_kernel(const float* __restrict__ in, const float* __restrict__ wgt,
                    const float* __restrict__ bias, float* __restrict__ out,
                    int Cin, int Cout, int Hin, int Win, int Hout, int Wout,
                    int tilesX, int doRelu)
{
    constexpr int TOX = 64, TOY = 16;
    constexpr int IW = (TOX - 1) * STRIDE + 3;   // 66 (s1) / 129 (s2)
    constexpr int IH = (TOY - 1) * STRIDE + 3;   // 18 (s1) / 33  (s2)

    __shared__ float s_in[IH * IW];
    __shared__ float s_w[128 * 9];               // Cin <= 128

    const int b    = blockIdx.z;
    const int co   = blockIdx.y;
    const int tile = blockIdx.x;
    const int oy0  = (tile / tilesX) * TOY;
    const int ox0  = (tile % tilesX) * TOX;
    const int tx   = threadIdx.x;                // 0..15
    const int ty   = threadIdx.y;                // 0..15
    const int tid  = ty * 16 + tx;

    // stage all weights for this output channel into smem
    const float* wB = wgt + (size_t)co * Cin * 9;
    for (int i = tid; i < Cin * 9; i += 256) s_w[i] = wB[i];

    const float* inB = in + (size_t)b * Cin * Hin * Win;
    const int iy0 = oy0 * STRIDE - 1;
    const int ix0 = ox0 * STRIDE - 1;

    float acc[4] = {0.f, 0.f, 0.f, 0.f};
    const int rbase = ty * STRIDE;
    const int cbase = tx * 4 * STRIDE;

    for (int ci = 0; ci < Cin; ++ci) {
        __syncthreads();   // protect s_in reuse (and s_w writes on first iter)
        const float* inC = inB + (size_t)ci * Hin * Win;
        for (int i = tid; i < IH * IW; i += 256) {
            int r = i / IW, c = i - r * IW;
            int iy = iy0 + r, ix = ix0 + c;
            float v = 0.f;
            if (iy >= 0 && iy < Hin && ix >= 0 && ix < Win)
                v = inC[(size_t)iy * Win + ix];
            s_in[i] = v;
        }
        __syncthreads();

        const float* wc = s_w + ci * 9;
        float w0 = wc[0], w1 = wc[1], w2 = wc[2];
        float w3 = wc[3], w4 = wc[4], w5 = wc[5];
        float w6 = wc[6], w7 = wc[7], w8 = wc[8];

        #pragma unroll
        for (int kr = 0; kr < 3; ++kr) {
            const float* row = s_in + (rbase + kr) * IW + cbase;
            float wr0 = (kr == 0) ? w0 : (kr == 1) ? w3 : w6;
            float wr1 = (kr == 0) ? w1 : (kr == 1) ? w4 : w7;
            float wr2 = (kr == 0) ? w2 : (kr == 1) ? w5 : w8;
            #pragma unroll
            for (int m = 0; m < 4; ++m) {
                acc[m] = fmaf(wr0, row[m * STRIDE + 0], acc[m]);
                acc[m] = fmaf(wr1, row[m * STRIDE + 1], acc[m]);
                acc[m] = fmaf(wr2, row[m * STRIDE + 2], acc[m]);
            }
        }
    }

    const int oy = oy0 + ty;
    if (oy < Hout) {
        float bv = bias ? bias[co] : 0.f;
        float* outB = out + ((size_t)b * Cout + co) * (size_t)Hout * Wout + (size_t)oy * Wout;
        #pragma unroll
        for (int m = 0; m < 4; ++m) {
            int ox = ox0 + tx * 4 + m;
            if (ox < Wout) {
                float v = acc[m] + bv;
                if (doRelu) v = fmaxf(v, 0.f);
                outB[ox] = v;
            }
        }
    }
}

// ---------------------------------------------------------------------------
// BN: deterministic two-stage reduction over (N, H, W) per channel.
// ---------------------------------------------------------------------------
__global__ __launch_bounds__(256)
void bn_partial_kernel(const float* __restrict__ x, float* __restrict__ psum,
                       float* __restrict__ psq, int C, int HW, int S)
{
    const int c = blockIdx.x;
    const int s = blockIdx.y;
    const long n = (long)B_ * HW;
    const long chunk = (n + S - 1) / S;
    const long lo = (long)s * chunk;
    const long hi = (lo + chunk < n) ? lo + chunk : n;

    float sum = 0.f, sq = 0.f;
    for (long i = lo + threadIdx.x; i < hi; i += 256) {
        long b = i / HW;
        int  p = (int)(i - b * HW);
        float v = x[(b * C + c) * (long)HW + p];
        sum += v;
        sq  += v * v;
    }
    __shared__ float ss[256], sQ[256];
    ss[threadIdx.x] = sum;
    sQ[threadIdx.x] = sq;
    __syncthreads();
    for (int step = 128; step > 0; step >>= 1) {
        if (threadIdx.x < step) {
            ss[threadIdx.x] += ss[threadIdx.x + step];
            sQ[threadIdx.x] += sQ[threadIdx.x + step];
        }
        __syncthreads();
    }
    if (threadIdx.x == 0) {
        psum[c * S + s] = ss[0];
        psq [c * S + s] = sQ[0];
    }
}

__global__ void bn_finalize_kernel(const float* __restrict__ psum, const float* __restrict__ psq,
                                   const float* __restrict__ g, const float* __restrict__ be,
                                   float* __restrict__ scale, float* __restrict__ shift,
                                   int S, float invN)
{
    const int c = blockIdx.x;
    __shared__ float ss[64], sQ[64];
    float a = 0.f, q = 0.f;
    if (threadIdx.x < S) { a = psum[c * S + threadIdx.x]; q = psq[c * S + threadIdx.x]; }
    ss[threadIdx.x] = a; sQ[threadIdx.x] = q;
    __syncthreads();
    for (int step = 32; step > 0; step >>= 1) {
        if (threadIdx.x < step) {
            ss[threadIdx.x] += ss[threadIdx.x + step];
            sQ[threadIdx.x] += sQ[threadIdx.x + step];
        }
        __syncthreads();
    }
    if (threadIdx.x == 0) {
        float mean = ss[0] * invN;
        float var  = sQ[0] * invN - mean * mean;
        float sc   = g[c] * rsqrtf(var + 1e-5f);
        scale[c] = sc;
        shift[c] = be[c] - mean * sc;
    }
}

__global__ __launch_bounds__(256)
void bn_apply_kernel(float* __restrict__ x, const float* __restrict__ scale,
                     const float* __restrict__ shift, int C, int HW, long total)
{
    long stride = (long)gridDim.x * blockDim.x;
    for (long i = (long)blockIdx.x * blockDim.x + threadIdx.x; i < total; i += stride) {
        int c = (int)((i / HW) % C);
        x[i] = x[i] * scale[c] + shift[c];
    }
}

// ---------------------------------------------------------------------------
// Deformable resample. Offsets consumed exactly as torch's flat view:
//   idx = (b*C + c)*HW + p  ->  di = off[2*idx], dj = off[2*idx + 1]
// ---------------------------------------------------------------------------
__global__ __launch_bounds__(256)
void deform_resample_kernel(const float* __restrict__ x, const float* __restrict__ off,
                            float* __restrict__ out, int H, int W, long total)
{
    const int HW = H * W;
    long stride = (long)gridDim.x * blockDim.x;
    for (long idx = (long)blockIdx.x * blockDim.x + threadIdx.x; idx < total; idx += stride) {
        long bc = idx / HW;
        int  p  = (int)(idx - bc * HW);
        int  i  = p / W;
        int  j  = p - i * W;
        float di = off[2 * idx];
        float dj = off[2 * idx + 1];
        float ci = fminf(fmaxf(di + (float)i, 0.f), (float)(H - 1));
        float cj = fminf(fmaxf(dj + (float)j, 0.f), (float)(W - 1));
        float fi0 = floorf(ci), fi1 = ceilf(ci);
        float fj0 = floorf(cj), fj1 = ceilf(cj);
        int i0 = (int)fi0, i1 = (int)fi1, j0 = (int)fj0, j1 = (int)fj1;
        const float* xb = x + bc * (long)HW;
        float v00 = xb[i0 * W + j0];
        float v10 = xb[i1 * W + j0];
        float v01 = xb[i0 * W + j1];
        float v11 = xb[i1 * W + j1];
        float ddi = ci - fi0, ddj = cj - fj0;
        float top = v00 + ddi * (v10 - v00);
        float bot = v01 + ddi * (v11 - v01);
        out[idx] = top + ddj * (bot - top);
    }
}

// ---------------------------------------------------------------------------
// Head: global avg pool (128, 28x28) -> FC 128->10 -> softmax. One block / batch.
// ---------------------------------------------------------------------------
__global__ __launch_bounds__(128)
void head_kernel(const float* __restrict__ a, const float* __restrict__ wfc,
                 const float* __restrict__ bfc, float* __restrict__ out)
{
    const int b = blockIdx.x;
    const int c = threadIdx.x;     // 0..127
    __shared__ float pool[128];
    __shared__ float logits[10];

    const float* p = a + ((size_t)b * 128 + c) * 784;
    float s = 0.f;
    for (int i = 0; i < 784; ++i) s += p[i];
    pool[c] = s * (1.f / 784.f);
    __syncthreads();

    if (c < 10) {
        float l = bfc[c];
        const float* w = wfc + c * 128;
        for (int k = 0; k < 128; ++k) l = fmaf(w[k], pool[k], l);
        logits[c] = l;
    }
    __syncthreads();

    if (c == 0) {
        float mx = logits[0];
        for (int r = 1; r < 10; ++r) mx = fmaxf(mx, logits[r]);
        float sum = 0.f;
        float e[10];
        for (int r = 0; r < 10; ++r) { e[r] = expf(logits[r] - mx); sum += e[r]; }
        float inv = 1.f / sum;
        for (int r = 0; r < 10; ++r) out[b * 10 + r] = e[r] * inv;
    }
}

// ---------------------------------------------------------------------------
// Host orchestration
// ---------------------------------------------------------------------------
static void run_conv(int stride, const float* in, const float* w, const float* bias,
                     float* out, int Cin, int Cout, int Hin, int Win, int doRelu)
{
    int Hout = (Hin - 1) / stride + 1;
    int Wout = (Win - 1) / stride + 1;
    int tilesX = (Wout + 63) / 64;
    int tilesY = (Hout + 15) / 16;
    dim3 grid(tilesX * tilesY, Cout, B_);
    dim3 block(16, 16);
    if (stride == 1)
        conv3x3_kernel<1><<<grid, block>>>(in, w, bias, out, Cin, Cout, Hin, Win, Hout, Wout, tilesX, doRelu);
    else
        conv3x3_kernel<2><<<grid, block>>>(in, w, bias, out, Cin, Cout, Hin, Win, Hout, Wout, tilesX, doRelu);
}

static void run_bn(float* act, int C, int HW, const float* g, const float* be,
                   float* psum, float* psq, float* scale, float* shift)
{
    const int S = 64;
    dim3 gp(C, S);
    bn_partial_kernel<<<gp, 256>>>(act, psum, psq, C, HW, S);
    bn_finalize_kernel<<<C, 64>>>(psum, psq, g, be, scale, shift, S, 1.f / ((float)B_ * HW));
    long total = (long)B_ * C * HW;
    bn_apply_kernel<<<2048, 256>>>(act, scale, shift, C, HW, total);
}

extern "C" void kernel_launch(void* const* d_in, const int* in_sizes, int n_in,
                              void* d_out, int out_size)
{
    (void)in_sizes; (void)n_in; (void)out_size;
    const float* x      = (const float*)d_in[0];
    const float* w11    = (const float*)d_in[1];
    const float* b11    = (const float*)d_in[2];
    const float* g11    = (const float*)d_in[3];
    const float* be11   = (const float*)d_in[4];
    const float* woff12 = (const float*)d_in[5];
    const float* w12    = (const float*)d_in[6];
    const float* b12    = (const float*)d_in[7];
    const float* g12    = (const float*)d_in[8];
    const float* be12   = (const float*)d_in[9];
    const float* woff21 = (const float*)d_in[10];
    const float* w21    = (const float*)d_in[11];
    const float* b21    = (const float*)d_in[12];
    const float* g21    = (const float*)d_in[13];
    const float* be21   = (const float*)d_in[14];
    const float* woff22 = (const float*)d_in[15];
    const float* w22    = (const float*)d_in[16];
    const float* b22    = (const float*)d_in[17];
    const float* g22    = (const float*)d_in[18];
    const float* be22   = (const float*)d_in[19];
    const float* wfc    = (const float*)d_in[20];
    const float* bfc    = (const float*)d_in[21];
    float* out = (float*)d_out;

    float* base = nullptr;
    cudaGetSymbolAddress((void**)&base, g_buf);

    float* A1   = base + OFF_A1;
    float* OFF1 = base + OFF_OFF1;
    float* D1   = base + OFF_D1;
    float* A2   = base + OFF_A2;
    float* OFF2 = base + OFF_OFF2;
    float* D2   = base + OFF_D2;
    float* A3   = base + OFF_A3;
    float* OFF3 = base + OFF_OFF3;
    float* D3   = base + OFF_D3;
    float* A4   = base + OFF_A4;
    float* PSUM = base + OFF_PSUM;
    float* PSQ  = base + OFF_PSQ;
    float* SC   = base + OFF_SC;
    float* SH   = base + OFF_SH;

    // ---- stage 1 @112x112 ----
    run_conv(1, x, w11, b11, A1, 1, 32, 112, 112, /*relu=*/1);
    run_bn(A1, 32, 112 * 112, g11, be11, PSUM, PSQ, SC, SH);

    run_conv(1, A1, woff12, nullptr, OFF1, 32, 64, 112, 112, 0);
    {
        long total = (long)B_ * 32 * 112 * 112;
        deform_resample_kernel<<<4096, 256>>>(A1, OFF1, D1, 112, 112, total);
    }

    // ---- stage 2: s2 conv -> 56x56 ----
    run_conv(2, D1, w12, b12, A2, 32, 64, 112, 112, 1);
    run_bn(A2, 64, 56 * 56, g12, be12, PSUM, PSQ, SC, SH);

    run_conv(1, A2, woff21, nullptr, OFF2, 64, 128, 56, 56, 0);
    {
        long total = (long)B_ * 64 * 56 * 56;
        deform_resample_kernel<<<4096, 256>>>(A2, OFF2, D2, 56, 56, total);
    }

    // ---- stage 3 @56x56 ----
    run_conv(1, D2, w21, b21, A3, 64, 128, 56, 56, 1);
    run_bn(A3, 128, 56 * 56, g21, be21, PSUM, PSQ, SC, SH);

    run_conv(1, A3, woff22, nullptr, OFF3, 128, 256, 56, 56, 0);
    {
        long total = (long)B_ * 128 * 56 * 56;
        deform_resample_kernel<<<4096, 256>>>(A3, OFF3, D3, 56, 56, total);
    }

    // ---- stage 4: s2 conv -> 28x28 ----
    run_conv(2, D3, w22, b22, A4, 128, 128, 56, 56, 1);
    run_bn(A4, 128, 28 * 28, g22, be22, PSUM, PSQ, SC, SH);

    // ---- head ----
    head_kernel<<<B_, 128>>>(A4, wfc, bfc, out);
}

// round 6
// speedup vs baseline: 4.2220x; 4.2220x over previous
#include <cuda_runtime.h>
#include <math.h>
#include <stdint.h>

// ---------------------------------------------------------------------------
// Shapes (fixed for this problem)
//   x:    (64, 1, 112, 112)
//   s1: conv 1->32 s1  @112 ; BN ; deform(32, off 64ch) @112
//   s2: conv 32->64 s2 @112->56 ; BN ; deform(64, off 128ch) @56
//   s3: conv 64->128 s1 @56 ; BN ; deform(128, off 256ch) @56
//   s4: conv 128->128 s2 @56->28 ; BN ; pool+fc+softmax -> (64,10) f32
// ---------------------------------------------------------------------------

#define B_ 64

// ---- scratch buffer (single __device__ global; offsets in floats) ----------
constexpr size_t SZ_A1   = (size_t)B_ * 32 * 112 * 112;
constexpr size_t SZ_OFF1 = (size_t)B_ * 64 * 112 * 112;
constexpr size_t SZ_D1   = SZ_A1;
constexpr size_t SZ_A2   = (size_t)B_ * 64 * 56 * 56;
constexpr size_t SZ_OFF2 = (size_t)B_ * 128 * 56 * 56;
constexpr size_t SZ_D2   = SZ_A2;
constexpr size_t SZ_A3   = (size_t)B_ * 128 * 56 * 56;
constexpr size_t SZ_OFF3 = (size_t)B_ * 256 * 56 * 56;
constexpr size_t SZ_D3   = SZ_A3;
constexpr size_t SZ_A4   = (size_t)B_ * 128 * 28 * 28;
constexpr size_t SZ_PART = (size_t)128 * 64;
constexpr size_t SZ_SS   = 128;

constexpr size_t OFF_A1   = 0;
constexpr size_t OFF_OFF1 = OFF_A1   + SZ_A1;
constexpr size_t OFF_D1   = OFF_OFF1 + SZ_OFF1;
constexpr size_t OFF_A2   = OFF_D1   + SZ_D1;
constexpr size_t OFF_OFF2 = OFF_A2   + SZ_A2;
constexpr size_t OFF_D2   = OFF_OFF2 + SZ_OFF2;
constexpr size_t OFF_A3   = OFF_D2   + SZ_D2;
constexpr size_t OFF_OFF3 = OFF_A3   + SZ_A3;
constexpr size_t OFF_D3   = OFF_OFF3 + SZ_OFF3;
constexpr size_t OFF_A4   = OFF_D3   + SZ_D3;
constexpr size_t OFF_PSUM = OFF_A4   + SZ_A4;
constexpr size_t OFF_PSQ  = OFF_PSUM + SZ_PART;
constexpr size_t OFF_SC   = OFF_PSQ  + SZ_PART;
constexpr size_t OFF_SH   = OFF_SC   + SZ_SS;
constexpr size_t TOTAL_F  = OFF_SH   + SZ_SS;

__device__ float g_buf[TOTAL_F];

// ---------------------------------------------------------------------------
// Direct 3x3 conv, pad=1, multi-output-channel register blocking.
// Block: 256 threads. Output tile: 32(x) x 8(y) pixels x 16 output channels.
// Each thread: 4 adjacent pixels x 4 output channels = 16 accumulators.
// Per cin per thread: 144 FMA vs ~54-63 LDS  -> FMA-pipe bound.
// Weights staged per 32-cin chunk; input tile double-buffered (1 sync / cin).
// ---------------------------------------------------------------------------
template <int STRIDE>
__global__ __launch_bounds__(256)
void conv3x3_mc_kernel(const float* __restrict__ in, const float* __restrict__ wgt,
                       const float* __restrict__ bias, float* __restrict__ out,
                       int Cin, int Cout, int Hin, int Win, int Hout, int Wout,
                       int tilesX, int doRelu)
{
    constexpr int TOX = 32, TOY = 8, KO = 16;
    constexpr int IW  = (TOX - 1) * STRIDE + 3;       // 34 (s1) / 65 (s2)
    constexpr int IWP = IW + 1;                       // pad: 35 / 66 (bank spread)
    constexpr int IH  = (TOY - 1) * STRIDE + 3;       // 10 / 17
    constexpr int CH  = 32;                           // cin chunk
    constexpr int NC  = 3 + 3 * STRIDE;               // input cols per thread: 6 / 9

    __shared__ float s_in[2][IH * IWP];
    __shared__ float s_w[CH * KO * 9];                // 18 KB

    const int b    = blockIdx.z;
    const int co0  = blockIdx.y * KO;
    const int tile = blockIdx.x;
    const int oy0  = (tile / tilesX) * TOY;
    const int ox0  = (tile % tilesX) * TOX;
    const int tid  = threadIdx.x;
    const int cog  = tid >> 6;          // 0..3  -> co group of 4
    const int ty   = (tid >> 3) & 7;    // 0..7  -> pixel row
    const int txg  = tid & 7;           // 0..7  -> pixel col group of 4

    const int iy0 = oy0 * STRIDE - 1;
    const int ix0 = ox0 * STRIDE - 1;
    const int rbase = ty * STRIDE;
    const int cbase = txg * 4 * STRIDE;

    float acc[4][4];
    #pragma unroll
    for (int m = 0; m < 4; ++m)
        #pragma unroll
        for (int p = 0; p < 4; ++p) acc[m][p] = 0.f;

    const float* inB = in + (size_t)b * Cin * Hin * Win;

    const int nch = (Cin + CH - 1) / CH;
    for (int ch = 0; ch < nch; ++ch) {
        const int cb  = ch * CH;
        const int ce  = (cb + CH < Cin) ? cb + CH : Cin;
        const int cnt = ce - cb;

        __syncthreads();   // previous chunk's compute must finish before s_w overwrite
        // stage weights for this chunk: layout [ci_local][co_local][k]
        for (int i = tid; i < cnt * KO * 9; i += 256) {
            int cl  = i / (KO * 9);
            int r   = i - cl * (KO * 9);
            int col = r / 9;
            int k   = r - col * 9;
            s_w[i] = wgt[((size_t)(co0 + col) * Cin + (cb + cl)) * 9 + k];
        }

        for (int ci = cb; ci < ce; ++ci) {
            const int bufi = ci & 1;
            const float* inC = inB + (size_t)ci * Hin * Win;
            #pragma unroll 2
            for (int i = tid; i < IH * IWP; i += 256) {
                int r = i / IWP, c = i - r * IWP;
                float v = 0.f;
                if (c < IW) {
                    int iy = iy0 + r, ix = ix0 + c;
                    if (iy >= 0 && iy < Hin && ix >= 0 && ix < Win)
                        v = inC[(size_t)iy * Win + ix];
                }
                s_in[bufi][i] = v;
            }
            __syncthreads();

            // load this thread's input window into registers
            float xv[3][NC];
            const float* bp = s_in[bufi] + rbase * IWP + cbase;
            #pragma unroll
            for (int kr = 0; kr < 3; ++kr)
                #pragma unroll
                for (int c = 0; c < NC; ++c)
                    xv[kr][c] = bp[kr * IWP + c];

            const float* wp = s_w + (ci - cb) * (KO * 9) + cog * 4 * 9;
            #pragma unroll
            for (int m = 0; m < 4; ++m) {
                #pragma unroll
                for (int kr = 0; kr < 3; ++kr) {
                    #pragma unroll
                    for (int kc = 0; kc < 3; ++kc) {
                        float w = wp[m * 9 + kr * 3 + kc];
                        #pragma unroll
                        for (int p = 0; p < 4; ++p)
                            acc[m][p] = fmaf(w, xv[kr][p * STRIDE + kc], acc[m][p]);
                    }
                }
            }
        }
    }

    // epilogue
    const int oy = oy0 + ty;
    if (oy < Hout) {
        #pragma unroll
        for (int m = 0; m < 4; ++m) {
            int co = co0 + cog * 4 + m;
            float bv = bias ? bias[co] : 0.f;
            float* outR = out + ((size_t)b * Cout + co) * (size_t)Hout * Wout
                              + (size_t)oy * Wout;
            #pragma unroll
            for (int p = 0; p < 4; ++p) {
                int ox = ox0 + txg * 4 + p;
                if (ox < Wout) {
                    float v = acc[m][p] + bv;
                    if (doRelu) v = fmaxf(v, 0.f);
                    outR[ox] = v;
                }
            }
        }
    }
}

// ---------------------------------------------------------------------------
// BN: deterministic two-stage reduction over (N, H, W) per channel.
// ---------------------------------------------------------------------------
__global__ __launch_bounds__(256)
void bn_partial_kernel(const float* __restrict__ x, float* __restrict__ psum,
                       float* __restrict__ psq, int C, int HW, int S)
{
    const int c = blockIdx.x;
    const int s = blockIdx.y;
    const long n = (long)B_ * HW;
    const long chunk = (n + S - 1) / S;
    const long lo = (long)s * chunk;
    const long hi = (lo + chunk < n) ? lo + chunk : n;

    float sum = 0.f, sq = 0.f;
    for (long i = lo + threadIdx.x; i < hi; i += 256) {
        long b = i / HW;
        int  p = (int)(i - b * HW);
        float v = x[(b * C + c) * (long)HW + p];
        sum += v;
        sq  += v * v;
    }
    __shared__ float ss[256], sQ[256];
    ss[threadIdx.x] = sum;
    sQ[threadIdx.x] = sq;
    __syncthreads();
    for (int step = 128; step > 0; step >>= 1) {
        if (threadIdx.x < step) {
            ss[threadIdx.x] += ss[threadIdx.x + step];
            sQ[threadIdx.x] += sQ[threadIdx.x + step];
        }
        __syncthreads();
    }
    if (threadIdx.x == 0) {
        psum[c * S + s] = ss[0];
        psq [c * S + s] = sQ[0];
    }
}

__global__ void bn_finalize_kernel(const float* __restrict__ psum, const float* __restrict__ psq,
                                   const float* __restrict__ g, const float* __restrict__ be,
                                   float* __restrict__ scale, float* __restrict__ shift,
                                   int S, float invN)
{
    const int c = blockIdx.x;
    __shared__ float ss[64], sQ[64];
    float a = 0.f, q = 0.f;
    if (threadIdx.x < S) { a = psum[c * S + threadIdx.x]; q = psq[c * S + threadIdx.x]; }
    ss[threadIdx.x] = a; sQ[threadIdx.x] = q;
    __syncthreads();
    for (int step = 32; step > 0; step >>= 1) {
        if (threadIdx.x < step) {
            ss[threadIdx.x] += ss[threadIdx.x + step];
            sQ[threadIdx.x] += sQ[threadIdx.x + step];
        }
        __syncthreads();
    }
    if (threadIdx.x == 0) {
        float mean = ss[0] * invN;
        float var  = sQ[0] * invN - mean * mean;
        float sc   = g[c] * rsqrtf(var + 1e-5f);
        scale[c] = sc;
        shift[c] = be[c] - mean * sc;
    }
}

__global__ __launch_bounds__(256)
void bn_apply_kernel(float* __restrict__ x, const float* __restrict__ scale,
                     const float* __restrict__ shift, int C, int HW, long total)
{
    long stride = (long)gridDim.x * blockDim.x;
    for (long i = (long)blockIdx.x * blockDim.x + threadIdx.x; i < total; i += stride) {
        int c = (int)((i / HW) % C);
        x[i] = x[i] * scale[c] + shift[c];
    }
}

// ---------------------------------------------------------------------------
// Deformable resample. Offsets consumed exactly as torch's flat view:
//   idx = (b*C + c)*HW + p  ->  di = off[2*idx], dj = off[2*idx + 1]
// ---------------------------------------------------------------------------
__global__ __launch_bounds__(256)
void deform_resample_kernel(const float* __restrict__ x, const float* __restrict__ off,
                            float* __restrict__ out, int H, int W, long total)
{
    const int HW = H * W;
    long stride = (long)gridDim.x * blockDim.x;
    for (long idx = (long)blockIdx.x * blockDim.x + threadIdx.x; idx < total; idx += stride) {
        long bc = idx / HW;
        int  p  = (int)(idx - bc * HW);
        int  i  = p / W;
        int  j  = p - i * W;
        float di = off[2 * idx];
        float dj = off[2 * idx + 1];
        float ci = fminf(fmaxf(di + (float)i, 0.f), (float)(H - 1));
        float cj = fminf(fmaxf(dj + (float)j, 0.f), (float)(W - 1));
        float fi0 = floorf(ci), fi1 = ceilf(ci);
        float fj0 = floorf(cj), fj1 = ceilf(cj);
        int i0 = (int)fi0, i1 = (int)fi1, j0 = (int)fj0, j1 = (int)fj1;
        const float* xb = x + bc * (long)HW;
        float v00 = xb[i0 * W + j0];
        float v10 = xb[i1 * W + j0];
        float v01 = xb[i0 * W + j1];
        float v11 = xb[i1 * W + j1];
        float ddi = ci - fi0, ddj = cj - fj0;
        float top = v00 + ddi * (v10 - v00);
        float bot = v01 + ddi * (v11 - v01);
        out[idx] = top + ddj * (bot - top);
    }
}

// ---------------------------------------------------------------------------
// Head: global avg pool (128, 28x28) -> FC 128->10 -> softmax. One block / batch.
// ---------------------------------------------------------------------------
__global__ __launch_bounds__(128)
void head_kernel(const float* __restrict__ a, const float* __restrict__ wfc,
                 const float* __restrict__ bfc, float* __restrict__ out)
{
    const int b = blockIdx.x;
    const int c = threadIdx.x;     // 0..127
    __shared__ float pool[128];
    __shared__ float logits[10];

    const float* p = a + ((size_t)b * 128 + c) * 784;
    float s = 0.f;
    for (int i = 0; i < 784; ++i) s += p[i];
    pool[c] = s * (1.f / 784.f);
    __syncthreads();

    if (c < 10) {
        float l = bfc[c];
        const float* w = wfc + c * 128;
        for (int k = 0; k < 128; ++k) l = fmaf(w[k], pool[k], l);
        logits[c] = l;
    }
    __syncthreads();

    if (c == 0) {
        float mx = logits[0];
        for (int r = 1; r < 10; ++r) mx = fmaxf(mx, logits[r]);
        float sum = 0.f;
        float e[10];
        for (int r = 0; r < 10; ++r) { e[r] = expf(logits[r] - mx); sum += e[r]; }
        float inv = 1.f / sum;
        for (int r = 0; r < 10; ++r) out[b * 10 + r] = e[r] * inv;
    }
}

// ---------------------------------------------------------------------------
// Host orchestration
// ---------------------------------------------------------------------------
static void run_conv(int stride, const float* in, const float* w, const float* bias,
                     float* out, int Cin, int Cout, int Hin, int Win, int doRelu)
{
    int Hout = (Hin - 1) / stride + 1;
    int Wout = (Win - 1) / stride + 1;
    int tilesX = (Wout + 31) / 32;
    int tilesY = (Hout + 7) / 8;
    dim3 grid(tilesX * tilesY, Cout / 16, B_);
    dim3 block(256);
    if (stride == 1)
        conv3x3_mc_kernel<1><<<grid, block>>>(in, w, bias, out, Cin, Cout, Hin, Win, Hout, Wout, tilesX, doRelu);
    else
        conv3x3_mc_kernel<2><<<grid, block>>>(in, w, bias, out, Cin, Cout, Hin, Win, Hout, Wout, tilesX, doRelu);
}

static void run_bn(float* act, int C, int HW, const float* g, const float* be,
                   float* psum, float* psq, float* scale, float* shift)
{
    const int S = 64;
    dim3 gp(C, S);
    bn_partial_kernel<<<gp, 256>>>(act, psum, psq, C, HW, S);
    bn_finalize_kernel<<<C, 64>>>(psum, psq, g, be, scale, shift, S, 1.f / ((float)B_ * HW));
    long total = (long)B_ * C * HW;
    bn_apply_kernel<<<2048, 256>>>(act, scale, shift, C, HW, total);
}

extern "C" void kernel_launch(void* const* d_in, const int* in_sizes, int n_in,
                              void* d_out, int out_size)
{
    (void)in_sizes; (void)n_in; (void)out_size;
    const float* x      = (const float*)d_in[0];
    const float* w11    = (const float*)d_in[1];
    const float* b11    = (const float*)d_in[2];
    const float* g11    = (const float*)d_in[3];
    const float* be11   = (const float*)d_in[4];
    const float* woff12 = (const float*)d_in[5];
    const float* w12    = (const float*)d_in[6];
    const float* b12    = (const float*)d_in[7];
    const float* g12    = (const float*)d_in[8];
    const float* be12   = (const float*)d_in[9];
    const float* woff21 = (const float*)d_in[10];
    const float* w21    = (const float*)d_in[11];
    const float* b21    = (const float*)d_in[12];
    const float* g21    = (const float*)d_in[13];
    const float* be21   = (const float*)d_in[14];
    const float* woff22 = (const float*)d_in[15];
    const float* w22    = (const float*)d_in[16];
    const float* b22    = (const float*)d_in[17];
    const float* g22    = (const float*)d_in[18];
    const float* be22   = (const float*)d_in[19];
    const float* wfc    = (const float*)d_in[20];
    const float* bfc    = (const float*)d_in[21];
    float* out = (float*)d_out;

    float* base = nullptr;
    cudaGetSymbolAddress((void**)&base, g_buf);

    float* A1   = base + OFF_A1;
    float* OFF1 = base + OFF_OFF1;
    float* D1   = base + OFF_D1;
    float* A2   = base + OFF_A2;
    float* OFF2 = base + OFF_OFF2;
    float* D2   = base + OFF_D2;
    float* A3   = base + OFF_A3;
    float* OFF3 = base + OFF_OFF3;
    float* D3   = base + OFF_D3;
    float* A4   = base + OFF_A4;
    float* PSUM = base + OFF_PSUM;
    float* PSQ  = base + OFF_PSQ;
    float* SC   = base + OFF_SC;
    float* SH   = base + OFF_SH;

    // ---- stage 1 @112x112 ----
    run_conv(1, x, w11, b11, A1, 1, 32, 112, 112, /*relu=*/1);
    run_bn(A1, 32, 112 * 112, g11, be11, PSUM, PSQ, SC, SH);

    run_conv(1, A1, woff12, nullptr, OFF1, 32, 64, 112, 112, 0);
    {
        long total = (long)B_ * 32 * 112 * 112;
        deform_resample_kernel<<<4096, 256>>>(A1, OFF1, D1, 112, 112, total);
    }

    // ---- stage 2: s2 conv -> 56x56 ----
    run_conv(2, D1, w12, b12, A2, 32, 64, 112, 112, 1);
    run_bn(A2, 64, 56 * 56, g12, be12, PSUM, PSQ, SC, SH);

    run_conv(1, A2, woff21, nullptr, OFF2, 64, 128, 56, 56, 0);
    {
        long total = (long)B_ * 64 * 56 * 56;
        deform_resample_kernel<<<4096, 256>>>(A2, OFF2, D2, 56, 56, total);
    }

    // ---- stage 3 @56x56 ----
    run_conv(1, D2, w21, b21, A3, 64, 128, 56, 56, 1);
    run_bn(A3, 128, 56 * 56, g21, be21, PSUM, PSQ, SC, SH);

    run_conv(1, A3, woff22, nullptr, OFF3, 128, 256, 56, 56, 0);
    {
        long total = (long)B_ * 128 * 56 * 56;
        deform_resample_kernel<<<4096, 256>>>(A3, OFF3, D3, 56, 56, total);
    }

    // ---- stage 4: s2 conv -> 28x28 ----
    run_conv(2, D3, w22, b22, A4, 128, 128, 56, 56, 1);
    run_bn(A4, 128, 28 * 28, g22, be22, PSUM, PSQ, SC, SH);

    // ---- head ----
    head_kernel<<<B_, 128>>>(A4, wfc, bfc, out);
}

// round 7
// speedup vs baseline: 6.2427x; 1.4786x over previous
#include <cuda_runtime.h>
#include <math.h>
#include <stdint.h>

// ---------------------------------------------------------------------------
// Shapes (fixed for this problem)
//   x:    (64, 1, 112, 112)
//   s1: conv 1->32 s1  @112 ; BN ; deform(32, off 64ch) @112
//   s2: conv 32->64 s2 @112->56 ; BN ; deform(64, off 128ch) @56
//   s3: conv 64->128 s1 @56 ; BN ; deform(128, off 256ch) @56
//   s4: conv 128->128 s2 @56->28 ; BN ; pool+fc+softmax -> (64,10) f32
// ---------------------------------------------------------------------------

#define B_ 64

// ---- scratch buffer (single __device__ global; offsets in floats) ----------
constexpr size_t SZ_A1   = (size_t)B_ * 32 * 112 * 112;
constexpr size_t SZ_OFF1 = (size_t)B_ * 64 * 112 * 112;
constexpr size_t SZ_D1   = SZ_A1;
constexpr size_t SZ_A2   = (size_t)B_ * 64 * 56 * 56;
constexpr size_t SZ_OFF2 = (size_t)B_ * 128 * 56 * 56;
constexpr size_t SZ_D2   = SZ_A2;
constexpr size_t SZ_A3   = (size_t)B_ * 128 * 56 * 56;
constexpr size_t SZ_OFF3 = (size_t)B_ * 256 * 56 * 56;
constexpr size_t SZ_D3   = SZ_A3;
constexpr size_t SZ_A4   = (size_t)B_ * 128 * 28 * 28;
constexpr size_t SZ_PART = (size_t)128 * 64;
constexpr size_t SZ_SS   = 128;

constexpr size_t OFF_A1   = 0;
constexpr size_t OFF_OFF1 = OFF_A1   + SZ_A1;
constexpr size_t OFF_D1   = OFF_OFF1 + SZ_OFF1;
constexpr size_t OFF_A2   = OFF_D1   + SZ_D1;
constexpr size_t OFF_OFF2 = OFF_A2   + SZ_A2;
constexpr size_t OFF_D2   = OFF_OFF2 + SZ_OFF2;
constexpr size_t OFF_A3   = OFF_D2   + SZ_D2;
constexpr size_t OFF_OFF3 = OFF_A3   + SZ_A3;
constexpr size_t OFF_D3   = OFF_OFF3 + SZ_OFF3;
constexpr size_t OFF_A4   = OFF_D3   + SZ_D3;
constexpr size_t OFF_PSUM = OFF_A4   + SZ_A4;
constexpr size_t OFF_PSQ  = OFF_PSUM + SZ_PART;
constexpr size_t OFF_SC   = OFF_PSQ  + SZ_PART;
constexpr size_t OFF_SH   = OFF_SC   + SZ_SS;
constexpr size_t TOTAL_F  = OFF_SH   + SZ_SS;

__device__ float g_buf[TOTAL_F];

// ---- packed fp32x2 helpers (Blackwell FFMA2 path; bit-exact fp32) ----------
typedef unsigned long long u64t;

__device__ __forceinline__ u64t pack2(float lo, float hi) {
    u64t d;
    asm("mov.b64 %0, {%1, %2};" : "=l"(d) : "f"(lo), "f"(hi));
    return d;
}
__device__ __forceinline__ void unpack2(u64t v, float& lo, float& hi) {
    asm("mov.b64 {%0, %1}, %2;" : "=f"(lo), "=f"(hi) : "l"(v));
}
__device__ __forceinline__ u64t fma2(u64t a, u64t b, u64t c) {
    u64t d;
    asm("fma.rn.f32x2 %0, %1, %2, %3;" : "=l"(d) : "l"(a), "l"(b), "l"(c));
    return d;
}

// ---------------------------------------------------------------------------
// Direct 3x3 conv, pad=1, FFMA2 + software-pipelined staging.
// Block: 256 threads. Output tile: 32(x) x 8(y) pixels x 32 output channels.
// Thread: 4 adjacent pixels x 8 co (4 co-pairs) = 16 f32x2 accumulators.
// Weights in smem as [ci_local][k][co] -> co-pair is a natural LDS.64 broadcast.
// Input tile double-buffered; next-next cin prefetched into registers.
// ---------------------------------------------------------------------------
template <int STRIDE>
__global__ __launch_bounds__(256)
void conv3x3_f2_kernel(const float* __restrict__ in, const float* __restrict__ wgt,
                       const float* __restrict__ bias, float* __restrict__ out,
                       int Cin, int Cout, int Hin, int Win, int Hout, int Wout,
                       int tilesX, int doRelu)
{
    constexpr int TOX = 32, TOY = 8, KO = 32, CH = 32;
    constexpr int IW  = (TOX - 1) * STRIDE + 3;   // 34 / 65
    constexpr int IWP = IW + 1;                   // 35 / 66
    constexpr int IH  = (TOY - 1) * STRIDE + 3;   // 10 / 17
    constexpr int NPIX  = IH * IWP;               // 350 / 1122
    constexpr int NSLOT = (NPIX + 255) / 256;     // 2 / 5
    constexpr int NC  = 3 + 3 * STRIDE;           // 6 / 9

    __shared__ float s_in[2][NPIX];
    __shared__ float s_w[CH * 9 * KO];            // 36 KB

    const int b    = blockIdx.z;
    const int co0  = blockIdx.y * KO;
    const int tile = blockIdx.x;
    const int oy0  = (tile / tilesX) * TOY;
    const int ox0  = (tile % tilesX) * TOX;
    const int tid  = threadIdx.x;
    const int cog  = tid >> 6;          // 0..3  -> 8 co's per thread
    const int ty   = (tid >> 3) & 7;    // 0..7  -> pixel row
    const int txg  = tid & 7;           // 0..7  -> pixel col group of 4

    const int iy0 = oy0 * STRIDE - 1;
    const int ix0 = ox0 * STRIDE - 1;
    const int rbase = ty * STRIDE;
    const int cbase = txg * 4 * STRIDE;
    const int HinWin = Hin * Win;

    // ---- per-thread staging slots: offsets + validity are ci-invariant ----
    int  soff[NSLOT];
    bool sval[NSLOT];   // load predicate (in-bounds)
    bool sput[NSLOT];   // store predicate (slot exists)
    #pragma unroll
    for (int s = 0; s < NSLOT; ++s) {
        int idx = tid + s * 256;
        int r = idx / IWP, c = idx - r * IWP;
        int iy = iy0 + r, ix = ix0 + c;
        sput[s] = (idx < NPIX);
        sval[s] = sput[s] && (c < IW) && iy >= 0 && iy < Hin && ix >= 0 && ix < Win;
        soff[s] = iy * Win + ix;
    }

    const float* inB = in + (size_t)b * Cin * HinWin;
    float rg[NSLOT];

    auto prefetch = [&](int ci) {
        const float* inC = inB + (size_t)ci * HinWin;
        #pragma unroll
        for (int s = 0; s < NSLOT; ++s)
            rg[s] = sval[s] ? __ldg(inC + soff[s]) : 0.f;
    };
    auto put = [&](int bufi) {
        #pragma unroll
        for (int s = 0; s < NSLOT; ++s)
            if (sput[s]) s_in[bufi][tid + s * 256] = rg[s];
    };
    auto stage_w = [&](int cb) {
        const int ce  = (cb + CH < Cin) ? cb + CH : Cin;
        const int cnt = ce - cb;
        for (int i = tid; i < cnt * 9 * KO; i += 256) {
            int col = i & (KO - 1);
            int t   = i >> 5;            // KO = 32
            int k   = t % 9;
            int cl  = t / 9;
            s_w[i] = wgt[((size_t)(co0 + col) * Cin + (cb + cl)) * 9 + k];
        }
    };

    u64t acc[4][4];
    #pragma unroll
    for (int mp = 0; mp < 4; ++mp)
        #pragma unroll
        for (int p = 0; p < 4; ++p) acc[mp][p] = 0ull;

    // ---- prologue: fill buf0 with cin 0, prefetch cin 1, stage chunk 0 ----
    prefetch(0);
    put(0);
    if (Cin > 1) prefetch(1);
    stage_w(0);
    __syncthreads();

    // ---- main loop: 1 barrier / cin (2 at chunk boundaries) ----
    for (int ci = 0; ci < Cin; ++ci) {
        if (ci + 1 < Cin) put((ci + 1) & 1);
        if (ci + 2 < Cin) prefetch(ci + 2);

        // compute cin ci
        {
            const int cl = ci & (CH - 1);
            const float* xp = s_in[ci & 1] + rbase * IWP + cbase;
            const float* wb = s_w + (cl * 9) * KO + cog * 8;
            #pragma unroll
            for (int kr = 0; kr < 3; ++kr) {
                u64t xs[NC];
                #pragma unroll
                for (int c = 0; c < NC; ++c) {
                    float v = xp[kr * IWP + c];
                    xs[c] = pack2(v, v);
                }
                const float* wr = wb + (kr * 3) * KO;
                #pragma unroll
                for (int kc = 0; kc < 3; ++kc) {
                    const float* wk = wr + kc * KO;
                    u64t w0 = *(const u64t*)(wk + 0);
                    u64t w1 = *(const u64t*)(wk + 2);
                    u64t w2 = *(const u64t*)(wk + 4);
                    u64t w3 = *(const u64t*)(wk + 6);
                    #pragma unroll
                    for (int p = 0; p < 4; ++p) {
                        u64t x = xs[p * STRIDE + kc];
                        acc[0][p] = fma2(w0, x, acc[0][p]);
                        acc[1][p] = fma2(w1, x, acc[1][p]);
                        acc[2][p] = fma2(w2, x, acc[2][p]);
                        acc[3][p] = fma2(w3, x, acc[3][p]);
                    }
                }
            }
        }

        if ((ci + 1) < Cin && ((ci + 1) & (CH - 1)) == 0) {
            __syncthreads();            // all readers of s_w chunk done
            stage_w(ci + 1);
        }
        __syncthreads();                // input STS (+ weights) visible
    }

    // ---- epilogue ----
    const int oy = oy0 + ty;
    if (oy < Hout) {
        #pragma unroll
        for (int mp = 0; mp < 4; ++mp) {
            int coL = co0 + cog * 8 + mp * 2;
            float bL = bias ? bias[coL] : 0.f;
            float bH = bias ? bias[coL + 1] : 0.f;
            float* oL = out + ((size_t)b * Cout + coL) * (size_t)Hout * Wout + (size_t)oy * Wout;
            float* oH = oL + (size_t)Hout * Wout;
            #pragma unroll
            for (int p = 0; p < 4; ++p) {
                int ox = ox0 + txg * 4 + p;
                if (ox < Wout) {
                    float lo, hi;
                    unpack2(acc[mp][p], lo, hi);
                    lo += bL; hi += bH;
                    if (doRelu) { lo = fmaxf(lo, 0.f); hi = fmaxf(hi, 0.f); }
                    oL[ox] = lo;
                    oH[ox] = hi;
                }
            }
        }
    }
}

// ---------------------------------------------------------------------------
// BN: deterministic two-stage reduction over (N, H, W) per channel.
// ---------------------------------------------------------------------------
__global__ __launch_bounds__(256)
void bn_partial_kernel(const float* __restrict__ x, float* __restrict__ psum,
                       float* __restrict__ psq, int C, int HW, int S)
{
    const int c = blockIdx.x;
    const int s = blockIdx.y;
    const long n = (long)B_ * HW;
    const long chunk = (n + S - 1) / S;
    const long lo = (long)s * chunk;
    const long hi = (lo + chunk < n) ? lo + chunk : n;

    float sum = 0.f, sq = 0.f;
    for (long i = lo + threadIdx.x; i < hi; i += 256) {
        long b = i / HW;
        int  p = (int)(i - b * HW);
        float v = x[(b * C + c) * (long)HW + p];
        sum += v;
        sq  += v * v;
    }
    __shared__ float ss[256], sQ[256];
    ss[threadIdx.x] = sum;
    sQ[threadIdx.x] = sq;
    __syncthreads();
    for (int step = 128; step > 0; step >>= 1) {
        if (threadIdx.x < step) {
            ss[threadIdx.x] += ss[threadIdx.x + step];
            sQ[threadIdx.x] += sQ[threadIdx.x + step];
        }
        __syncthreads();
    }
    if (threadIdx.x == 0) {
        psum[c * S + s] = ss[0];
        psq [c * S + s] = sQ[0];
    }
}

__global__ void bn_finalize_kernel(const float* __restrict__ psum, const float* __restrict__ psq,
                                   const float* __restrict__ g, const float* __restrict__ be,
                                   float* __restrict__ scale, float* __restrict__ shift,
                                   int S, float invN)
{
    const int c = blockIdx.x;
    __shared__ float ss[64], sQ[64];
    float a = 0.f, q = 0.f;
    if (threadIdx.x < S) { a = psum[c * S + threadIdx.x]; q = psq[c * S + threadIdx.x]; }
    ss[threadIdx.x] = a; sQ[threadIdx.x] = q;
    __syncthreads();
    for (int step = 32; step > 0; step >>= 1) {
        if (threadIdx.x < step) {
            ss[threadIdx.x] += ss[threadIdx.x + step];
            sQ[threadIdx.x] += sQ[threadIdx.x + step];
        }
        __syncthreads();
    }
    if (threadIdx.x == 0) {
        float mean = ss[0] * invN;
        float var  = sQ[0] * invN - mean * mean;
        float sc   = g[c] * rsqrtf(var + 1e-5f);
        scale[c] = sc;
        shift[c] = be[c] - mean * sc;
    }
}

__global__ __launch_bounds__(256)
void bn_apply_kernel(float* __restrict__ x, const float* __restrict__ scale,
                     const float* __restrict__ shift, int C, int HW, long total)
{
    long stride = (long)gridDim.x * blockDim.x;
    for (long i = (long)blockIdx.x * blockDim.x + threadIdx.x; i < total; i += stride) {
        int c = (int)((i / HW) % C);
        x[i] = x[i] * scale[c] + shift[c];
    }
}

// ---------------------------------------------------------------------------
// Deformable resample. Offsets consumed exactly as torch's flat view:
//   idx = (b*C + c)*HW + p  ->  di = off[2*idx], dj = off[2*idx + 1]
// ---------------------------------------------------------------------------
__global__ __launch_bounds__(256)
void deform_resample_kernel(const float* __restrict__ x, const float* __restrict__ off,
                            float* __restrict__ out, int H, int W, long total)
{
    const int HW = H * W;
    long stride = (long)gridDim.x * blockDim.x;
    for (long idx = (long)blockIdx.x * blockDim.x + threadIdx.x; idx < total; idx += stride) {
        long bc = idx / HW;
        int  p  = (int)(idx - bc * HW);
        int  i  = p / W;
        int  j  = p - i * W;
        float di = off[2 * idx];
        float dj = off[2 * idx + 1];
        float ci = fminf(fmaxf(di + (float)i, 0.f), (float)(H - 1));
        float cj = fminf(fmaxf(dj + (float)j, 0.f), (float)(W - 1));
        float fi0 = floorf(ci), fi1 = ceilf(ci);
        float fj0 = floorf(cj), fj1 = ceilf(cj);
        int i0 = (int)fi0, i1 = (int)fi1, j0 = (int)fj0, j1 = (int)fj1;
        const float* xb = x + bc * (long)HW;
        float v00 = xb[i0 * W + j0];
        float v10 = xb[i1 * W + j0];
        float v01 = xb[i0 * W + j1];
        float v11 = xb[i1 * W + j1];
        float ddi = ci - fi0, ddj = cj - fj0;
        float top = v00 + ddi * (v10 - v00);
        float bot = v01 + ddi * (v11 - v01);
        out[idx] = top + ddj * (bot - top);
    }
}

// ---------------------------------------------------------------------------
// Head: global avg pool (128, 28x28) -> FC 128->10 -> softmax. One block / batch.
// ---------------------------------------------------------------------------
__global__ __launch_bounds__(128)
void head_kernel(const float* __restrict__ a, const float* __restrict__ wfc,
                 const float* __restrict__ bfc, float* __restrict__ out)
{
    const int b = blockIdx.x;
    const int c = threadIdx.x;     // 0..127
    __shared__ float pool[128];
    __shared__ float logits[10];

    const float* p = a + ((size_t)b * 128 + c) * 784;
    float s = 0.f;
    for (int i = 0; i < 784; ++i) s += p[i];
    pool[c] = s * (1.f / 784.f);
    __syncthreads();

    if (c < 10) {
        float l = bfc[c];
        const float* w = wfc + c * 128;
        for (int k = 0; k < 128; ++k) l = fmaf(w[k], pool[k], l);
        logits[c] = l;
    }
    __syncthreads();

    if (c == 0) {
        float mx = logits[0];
        for (int r = 1; r < 10; ++r) mx = fmaxf(mx, logits[r]);
        float sum = 0.f;
        float e[10];
        for (int r = 0; r < 10; ++r) { e[r] = expf(logits[r] - mx); sum += e[r]; }
        float inv = 1.f / sum;
        for (int r = 0; r < 10; ++r) out[b * 10 + r] = e[r] * inv;
    }
}

// ---------------------------------------------------------------------------
// Host orchestration
// ---------------------------------------------------------------------------
static void run_conv(int stride, const float* in, const float* w, const float* bias,
                     float* out, int Cin, int Cout, int Hin, int Win, int doRelu)
{
    int Hout = (Hin - 1) / stride + 1;
    int Wout = (Win - 1) / stride + 1;
    int tilesX = (Wout + 31) / 32;
    int tilesY = (Hout + 7) / 8;
    dim3 grid(tilesX * tilesY, Cout / 32, B_);
    dim3 block(256);
    if (stride == 1)
        conv3x3_f2_kernel<1><<<grid, block>>>(in, w, bias, out, Cin, Cout, Hin, Win, Hout, Wout, tilesX, doRelu);
    else
        conv3x3_f2_kernel<2><<<grid, block>>>(in, w, bias, out, Cin, Cout, Hin, Win, Hout, Wout, tilesX, doRelu);
}

static void run_bn(float* act, int C, int HW, const float* g, const float* be,
                   float* psum, float* psq, float* scale, float* shift)
{
    const int S = 64;
    dim3 gp(C, S);
    bn_partial_kernel<<<gp, 256>>>(act, psum, psq, C, HW, S);
    bn_finalize_kernel<<<C, 64>>>(psum, psq, g, be, scale, shift, S, 1.f / ((float)B_ * HW));
    long total = (long)B_ * C * HW;
    bn_apply_kernel<<<2048, 256>>>(act, scale, shift, C, HW, total);
}

extern "C" void kernel_launch(void* const* d_in, const int* in_sizes, int n_in,
                              void* d_out, int out_size)
{
    (void)in_sizes; (void)n_in; (void)out_size;
    const float* x      = (const float*)d_in[0];
    const float* w11    = (const float*)d_in[1];
    const float* b11    = (const float*)d_in[2];
    const float* g11    = (const float*)d_in[3];
    const float* be11   = (const float*)d_in[4];
    const float* woff12 = (const float*)d_in[5];
    const float* w12    = (const float*)d_in[6];
    const float* b12    = (const float*)d_in[7];
    const float* g12    = (const float*)d_in[8];
    const float* be12   = (const float*)d_in[9];
    const float* woff21 = (const float*)d_in[10];
    const float* w21    = (const float*)d_in[11];
    const float* b21    = (const float*)d_in[12];
    const float* g21    = (const float*)d_in[13];
    const float* be21   = (const float*)d_in[14];
    const float* woff22 = (const float*)d_in[15];
    const float* w22    = (const float*)d_in[16];
    const float* b22    = (const float*)d_in[17];
    const float* g22    = (const float*)d_in[18];
    const float* be22   = (const float*)d_in[19];
    const float* wfc    = (const float*)d_in[20];
    const float* bfc    = (const float*)d_in[21];
    float* out = (float*)d_out;

    float* base = nullptr;
    cudaGetSymbolAddress((void**)&base, g_buf);

    float* A1   = base + OFF_A1;
    float* OFF1 = base + OFF_OFF1;
    float* D1   = base + OFF_D1;
    float* A2   = base + OFF_A2;
    float* OFF2 = base + OFF_OFF2;
    float* D2   = base + OFF_D2;
    float* A3   = base + OFF_A3;
    float* OFF3 = base + OFF_OFF3;
    float* D3   = base + OFF_D3;
    float* A4   = base + OFF_A4;
    float* PSUM = base + OFF_PSUM;
    float* PSQ  = base + OFF_PSQ;
    float* SC   = base + OFF_SC;
    float* SH   = base + OFF_SH;

    // ---- stage 1 @112x112 ----
    run_conv(1, x, w11, b11, A1, 1, 32, 112, 112, /*relu=*/1);
    run_bn(A1, 32, 112 * 112, g11, be11, PSUM, PSQ, SC, SH);

    run_conv(1, A1, woff12, nullptr, OFF1, 32, 64, 112, 112, 0);
    {
        long total = (long)B_ * 32 * 112 * 112;
        deform_resample_kernel<<<4096, 256>>>(A1, OFF1, D1, 112, 112, total);
    }

    // ---- stage 2: s2 conv -> 56x56 ----
    run_conv(2, D1, w12, b12, A2, 32, 64, 112, 112, 1);
    run_bn(A2, 64, 56 * 56, g12, be12, PSUM, PSQ, SC, SH);

    run_conv(1, A2, woff21, nullptr, OFF2, 64, 128, 56, 56, 0);
    {
        long total = (long)B_ * 64 * 56 * 56;
        deform_resample_kernel<<<4096, 256>>>(A2, OFF2, D2, 56, 56, total);
    }

    // ---- stage 3 @56x56 ----
    run_conv(1, D2, w21, b21, A3, 64, 128, 56, 56, 1);
    run_bn(A3, 128, 56 * 56, g21, be21, PSUM, PSQ, SC, SH);

    run_conv(1, A3, woff22, nullptr, OFF3, 128, 256, 56, 56, 0);
    {
        long total = (long)B_ * 128 * 56 * 56;
        deform_resample_kernel<<<4096, 256>>>(A3, OFF3, D3, 56, 56, total);
    }

    // ---- stage 4: s2 conv -> 28x28 ----
    run_conv(2, D3, w22, b22, A4, 128, 128, 56, 56, 1);
    run_bn(A4, 128, 28 * 28, g22, be22, PSUM, PSQ, SC, SH);

    // ---- head ----
    head_kernel<<<B_, 128>>>(A4, wfc, bfc, out);
}